// round 16
// baseline (speedup 1.0000x reference)
#include <cuda_runtime.h>
#include <cuda_bf16.h>
#include <math.h>
#include <stdint.h>

#define Cn   256
#define Hn   128
#define Wn   128
#define Bn   2
#define HWn  (Hn*Wn)        // 16384
#define NPIX (Bn*HWn)       // 32768
#define NCn  80
#define Kdcn 2304
#define WSZ  (Cn*Kdcn)      // 589824 weights per layer
#define NCHUNK 72
#define NELEM (Bn*Cn*HWn)   // 8388608
#define PKQ  (NELEM/4)

// GEMM stage: A hi/lo planes 128oc x 64B, B hi/lo planes 128px x 64B
#define CAH 0
#define CAL 8192
#define CBH 16384
#define CBL 24576
#define CSTG 32768
#define CONV_SMEM (2*CSTG)            // 65536 (epilogue reuses as 64KB staging)

typedef __nv_bfloat16 bf16;

__device__ __forceinline__ uint32_t smem_to_u32(const void* p) {
    uint32_t a;
    asm("{ .reg .u64 t; cvta.to.shared.u64 t, %1; cvt.u32.u64 %0, t; }" : "=r"(a) : "l"(p));
    return a;
}
__device__ __forceinline__ void cpasync16(uint32_t dst, const void* src, uint32_t srcsz) {
    asm volatile("cp.async.cg.shared.global [%0], [%1], 16, %2;"
        :: "r"(dst), "l"(src), "r"(srcsz) : "memory");
}
__device__ __forceinline__ void cpcommit() {
    asm volatile("cp.async.commit_group;" ::: "memory");
}
__device__ __forceinline__ void cpwait0() {
    asm volatile("cp.async.wait_group 0;" ::: "memory");
}
__device__ __forceinline__ void ldsm4(uint32_t r[4], uint32_t addr) {
    asm volatile("ldmatrix.sync.aligned.m8n8.x4.shared.b16 {%0,%1,%2,%3}, [%4];"
        : "=r"(r[0]), "=r"(r[1]), "=r"(r[2]), "=r"(r[3]) : "r"(addr));
}
__device__ __forceinline__ void mma16816(float d[4], const uint32_t a[4],
                                         uint32_t b0, uint32_t b1) {
    asm volatile(
        "mma.sync.aligned.m16n8k16.row.col.f32.bf16.bf16.f32 "
        "{%0,%1,%2,%3}, {%4,%5,%6,%7}, {%8,%9}, {%0,%1,%2,%3};"
        : "+f"(d[0]), "+f"(d[1]), "+f"(d[2]), "+f"(d[3])
        : "r"(a[0]), "r"(a[1]), "r"(a[2]), "r"(a[3]), "r"(b0), "r"(b1));
}
__device__ __forceinline__ uint32_t prmt(uint32_t a, uint32_t b, uint32_t sel) {
    uint32_t d; asm("prmt.b32 %0,%1,%2,%3;" : "=r"(d) : "r"(a), "r"(b), "r"(sel));
    return d;
}
// packed word: low16 = bf16(v), high16 = bf16(v - bf16(v))
__device__ __forceinline__ uint32_t packpair(float v) {
    bf16 h = __float2bfloat16(v);
    float hf = __bfloat162float(h);
    bf16 l = __float2bfloat16(v - hf);
    uint16_t hb = *reinterpret_cast<uint16_t*>(&h);
    uint16_t lb = *reinterpret_cast<uint16_t*>(&l);
    return (uint32_t)hb | ((uint32_t)lb << 16);
}
__device__ __forceinline__ float bflo(uint32_t w) { return __int_as_float(w << 16); }
__device__ __forceinline__ float bfhi(uint32_t w) { return __int_as_float(w & 0xFFFF0000u); }

// ---------------- scratch: hi/lo bf16 plane maps, channel-last [pix][256] ----------------
__device__ __align__(16) bf16 g_xH [NELEM];
__device__ __align__(16) bf16 g_xL [NELEM];
__device__ __align__(16) bf16 g_aH [NELEM];
__device__ __align__(16) bf16 g_aL [NELEM];
__device__ __align__(16) bf16 g_bH [NELEM];
__device__ __align__(16) bf16 g_bL [NELEM];
__device__ __align__(16) bf16 g_cH [NELEM];
__device__ __align__(16) bf16 g_cL [NELEM];
__device__ __align__(16) bf16 g_dH [NELEM];
__device__ __align__(16) bf16 g_dL [NELEM];
__device__ __align__(16) bf16 g_clsH[NELEM];
__device__ __align__(16) bf16 g_clsL[NELEM];
__device__ __align__(16) bf16 g_ptsH[NELEM];
__device__ __align__(16) bf16 g_ptsL[NELEM];
__device__ float g_off [Bn*27*HWn];
__device__ float g_dcn0[(size_t)Cn*NPIX];
__device__ float g_dcn1[(size_t)Cn*NPIX];
__device__ __align__(16) bf16 g_wH[9*WSZ];
__device__ __align__(16) bf16 g_wL[9*WSZ];
// im2col sampled tensors for the two dcns: [px][2304] hi/lo planes
__device__ __align__(16) bf16 g_s0H[(size_t)NPIX*Kdcn];
__device__ __align__(16) bf16 g_s0L[(size_t)NPIX*Kdcn];
__device__ __align__(16) bf16 g_s1H[(size_t)NPIX*Kdcn];
__device__ __align__(16) bf16 g_s1L[(size_t)NPIX*Kdcn];

struct WPtrs { const float* w[9]; };

// ---------------- prep: plane-split x + all 9 weights (one launch) ----------------
__global__ void __launch_bounds__(256)
prep_kernel(const float* __restrict__ x, WPtrs wp,
            bf16* __restrict__ xH, bf16* __restrict__ xL,
            bf16* __restrict__ wH, bf16* __restrict__ wL)
{
    int gid = blockIdx.x * 256 + threadIdx.x;
    if (gid < PKQ) {
        int hw  = gid & (HWn - 1);
        int rem = gid >> 14;
        int cg  = rem & 63;
        int b   = rem >> 6;
        const float* src = x + ((size_t)(b*Cn + cg*4))*HWn + hw;
        uint32_t pk0 = packpair(__ldg(src));
        uint32_t pk1 = packpair(__ldg(src + HWn));
        uint32_t pk2 = packpair(__ldg(src + 2*HWn));
        uint32_t pk3 = packpair(__ldg(src + 3*HWn));
        uint2 hv = { prmt(pk0, pk1, 0x5410), prmt(pk2, pk3, 0x5410) };
        uint2 lv = { prmt(pk0, pk1, 0x7632), prmt(pk2, pk3, 0x7632) };
        size_t o = (size_t)(b*HWn + hw)*256 + cg*4;
        *reinterpret_cast<uint2*>(xH + o) = hv;
        *reinterpret_cast<uint2*>(xL + o) = lv;
    } else {
        int i = gid - PKQ;                 // < 9*WSZ
        int l = i / WSZ, r = i - l*WSZ;
        int oc = r / Kdcn, kp = r - oc*Kdcn;
        int tap = kp >> 8, ic = kp & 255;
        float v = wp.w[l][((size_t)oc*256 + ic)*9 + tap];
        bf16 h = __float2bfloat16(v);
        wH[i] = h;
        wL[i] = __float2bfloat16(v - __bfloat162float(h));
    }
}

// =====================================================================
// Dual-job conv3x3, 3-plane MMA, 2x2 warp grid of 64x64 tiles.
// 128 threads/CTA, 2 CTA/SM. Grid (256, 2, 2).
// =====================================================================
struct ConvJob {
    const bf16* inH; const bf16* inL;
    const bf16* wH;  const bf16* wL;
    const float* bias;
    bf16* outH; bf16* outL;
};

__global__ void __launch_bounds__(128, 2)
conv_kernel(ConvJob j0, ConvJob j1)
{
    extern __shared__ __align__(128) char smem[];
    const ConvJob J = blockIdx.z ? j1 : j0;
    const uint32_t sbase = smem_to_u32(smem);
    const int tid  = threadIdx.x;
    const int wid  = tid >> 5, lane = tid & 31;
    const int nblk = blockIdx.x;
    const int b = nblk >> 7, y = nblk & 127;
    const int ocbase = blockIdx.y * 128;

    const int m0 = (wid & 1) * 64;      // 2 m-warps x 64 oc
    const int n0 = (wid >> 1) * 64;     // 2 n-warps x 64 px
    const int l7   = lane & 7;
    const int aR   = l7 + ((lane >> 3) & 1) * 8;
    const int bpx  = l7 + (lane >> 4) * 8;
    const int qA0  = (lane >> 4);
    const int qB0  = ((lane >> 3) & 1);
    const int swzL = (l7 >> 1) & 3;

    float acc[32][4];
    #pragma unroll
    for (int i = 0; i < 32; i++)
        #pragma unroll
        for (int j = 0; j < 4; j++) acc[i][j] = 0.f;

    auto load_chunk = [&](int stg, int cc) {
        const uint32_t su = sbase + stg * CSTG;
        {   // A: 128 oc rows x 64B per plane; thread = row
            int row = tid;
            int sw = (row >> 1) & 3;
            const bf16* sH = J.wH + (size_t)(ocbase + row) * Kdcn + cc * 32;
            const bf16* sL = J.wL + (size_t)(ocbase + row) * Kdcn + cc * 32;
            uint32_t drow = su + row * 64;
            #pragma unroll
            for (int ch = 0; ch < 4; ch++) {
                uint32_t off = (uint32_t)((ch ^ sw) << 4);
                cpasync16(drow + CAH + off, sH + ch*8, 16);
                cpasync16(drow + CAL + off, sL + ch*8, 16);
            }
        }
        const int tap = cc >> 3;
        const int ic0 = (cc & 7) * 32;
        const int ky = tap / 3 - 1, kx = tap % 3 - 1;
        int p = tid;
        int yy = y + ky, xx = p + kx;
        bool ok = (yy >= 0 && yy < Hn && xx >= 0 && xx < Wn);
        size_t so = (size_t)(b*HWn + yy*Wn + xx)*256 + ic0;
        uint32_t srcsz = ok ? 16u : 0u;
        int sw = (p >> 1) & 3;
        uint32_t drow = su + p * 64;
        #pragma unroll
        for (int ch = 0; ch < 4; ch++) {
            uint32_t off = (uint32_t)((ch ^ sw) << 4);
            cpasync16(drow + CBH + off, J.inH + so + ch*8, srcsz);
            cpasync16(drow + CBL + off, J.inL + so + ch*8, srcsz);
        }
        cpcommit();
    };

    auto compute = [&](int stg) {
        const uint32_t Sb = sbase + stg*CSTG;
        #pragma unroll
        for (int ks = 0; ks < 2; ks++) {
            uint32_t qa = (uint32_t)(((ks*2 + qA0) ^ swzL) << 4);
            uint32_t qb = (uint32_t)(((ks*2 + qB0) ^ swzL) << 4);
            uint32_t bh[4][4], bl[4][4];
            #pragma unroll
            for (int nb = 0; nb < 4; nb++) {
                uint32_t bRow = (uint32_t)((n0 + nb*16 + bpx) * 64);
                ldsm4(bh[nb], Sb + CBH + bRow + qb);
                ldsm4(bl[nb], Sb + CBL + bRow + qb);
            }
            #pragma unroll
            for (int mf = 0; mf < 4; mf++) {
                uint32_t aRow = (uint32_t)((m0 + mf*16 + aR) * 64);
                uint32_t ah[4], al[4];
                ldsm4(ah, Sb + CAH + aRow + qa);
                ldsm4(al, Sb + CAL + aRow + qa);
                #pragma unroll
                for (int nb = 0; nb < 4; nb++) {
                    int ai = mf*8 + nb*2;
                    mma16816(acc[ai],     ah, bh[nb][0], bh[nb][1]);
                    mma16816(acc[ai + 1], ah, bh[nb][2], bh[nb][3]);
                    mma16816(acc[ai],     ah, bl[nb][0], bl[nb][1]);
                    mma16816(acc[ai + 1], ah, bl[nb][2], bl[nb][3]);
                    mma16816(acc[ai],     al, bh[nb][0], bh[nb][1]);
                    mma16816(acc[ai + 1], al, bh[nb][2], bh[nb][3]);
                }
            }
        }
    };

    load_chunk(0, 0);
    cpwait0();
    __syncthreads();
    for (int c = 0; c < NCHUNK; c++) {
        int cur = c & 1;
        if (c + 1 < NCHUNK) load_chunk(cur ^ 1, c + 1);
        compute(cur);
        cpwait0();
        __syncthreads();
    }

    // epilogue: stage packed words in smem [px][128 words swizzled], then split to planes
    const int r  = lane >> 2;
    const int c2 = (lane & 3) * 2;
    __syncthreads();
    uint32_t* st = reinterpret_cast<uint32_t*>(smem);
    #pragma unroll
    for (int mf = 0; mf < 4; mf++) {
        #pragma unroll
        for (int rr = 0; rr < 2; rr++) {
            int oc_l = m0 + mf*16 + r + rr*8;
            float bv = __ldg(&J.bias[ocbase + oc_l]);
            #pragma unroll
            for (int nb = 0; nb < 4; nb++) {
                #pragma unroll
                for (int h = 0; h < 2; h++) {
                    float* d = acc[mf*8 + nb*2 + h];
                    int x0 = n0 + nb*16 + h*8 + c2;
                    float v0 = fmaxf(d[rr*2]   + bv, 0.f);
                    float v1 = fmaxf(d[rr*2+1] + bv, 0.f);
                    st[x0*128     + (oc_l ^ ((x0     & 7) << 2))] = packpair(v0);
                    st[(x0+1)*128 + (oc_l ^ (((x0+1) & 7) << 2))] = packpair(v1);
                }
            }
        }
    }
    __syncthreads();
    {
        int p = tid;
        int sw = (p & 7) << 2;
        #pragma unroll
        for (int half = 0; half < 2; half++) {
            size_t o = (size_t)(b*HWn + y*Wn + p)*256 + ocbase + half*64;
            #pragma unroll
            for (int j4 = 0; j4 < 16; j4++) {
                int w = half*64 + j4*4;
                uint4 v = *reinterpret_cast<const uint4*>(st + p*128 + (w ^ sw));
                uint2 hv = { prmt(v.x, v.y, 0x5410), prmt(v.z, v.w, 0x5410) };
                uint2 lv = { prmt(v.x, v.y, 0x7632), prmt(v.z, v.w, 0x7632) };
                *reinterpret_cast<uint2*>(J.outH + o + j4*4) = hv;
                *reinterpret_cast<uint2*>(J.outL + o + j4*4) = lv;
            }
        }
    }
}

// =====================================================================
// Standalone dual-job bilinear gather -> im2col planes samp[px][2304].
// Warp = one (tap, pixel); lane = 8-channel group.
// grid (9*NPIX/8 = 36864, 1, 2), 256 threads (8 warps/block).
// =====================================================================
__global__ void __launch_bounds__(256)
gather_kernel(const bf16* __restrict__ f0H, const bf16* __restrict__ f0L,
              const bf16* __restrict__ f1H, const bf16* __restrict__ f1L,
              const float* __restrict__ off,
              bf16* __restrict__ s0H, bf16* __restrict__ s0L,
              bf16* __restrict__ s1H, bf16* __restrict__ s1L)
{
    const int z = blockIdx.z;
    const bf16* featH = z ? f1H : f0H;
    const bf16* featL = z ? f1L : f0L;
    bf16* sH = z ? s1H : s0H;
    bf16* sL = z ? s1L : s0L;
    const bool use_mask = (z == 0);

    int gw   = blockIdx.x * 8 + (threadIdx.x >> 5);   // [0, 9*NPIX) warp id
    int lane = threadIdx.x & 31;
    int tap  = gw >> 15;
    int pg   = gw & (NPIX - 1);
    int b  = pg >> 14;
    int hw = pg & (HWn - 1);
    int y  = hw >> 7, x = hw & 127;
    int ky = tap / 3 - 1, kx = tap % 3 - 1;

    const float* offb = off + (size_t)b*27*HWn + hw;
    float offy = __ldg(offb + (size_t)(2*tap)*HWn);
    float offx = __ldg(offb + (size_t)(2*tap + 1)*HWn);
    float py = (float)(y + ky) + offy;
    float px = (float)(x + kx) + offx;
    float fy0 = floorf(py), fx0 = floorf(px);
    float ly = py - fy0, lx = px - fx0;
    bool vy0 = (fy0 >= 0.f)       && (fy0 <= 127.f);
    bool vy1 = (fy0 + 1.f >= 0.f) && (fy0 + 1.f <= 127.f);
    bool vx0 = (fx0 >= 0.f)       && (fx0 <= 127.f);
    bool vx1 = (fx0 + 1.f >= 0.f) && (fx0 + 1.f <= 127.f);
    float w00 = (1.f-ly)*(1.f-lx) * ((vy0 && vx0) ? 1.f : 0.f);
    float w01 = (1.f-ly)*lx       * ((vy0 && vx1) ? 1.f : 0.f);
    float w10 = ly*(1.f-lx)       * ((vy1 && vx0) ? 1.f : 0.f);
    float w11 = ly*lx             * ((vy1 && vx1) ? 1.f : 0.f);
    if (use_mask) {
        float m = __ldg(offb + (size_t)(18 + tap)*HWn);
        w00 *= m; w01 *= m; w10 *= m; w11 *= m;
    }
    int iy0 = min(max((int)fy0,     0), Hn-1);
    int iy1 = min(max((int)fy0 + 1, 0), Hn-1);
    int ix0 = min(max((int)fx0,     0), Wn-1);
    int ix1 = min(max((int)fx0 + 1, 0), Wn-1);
    size_t i00 = (size_t)(b*HWn + iy0*Wn + ix0)*256;
    size_t i01 = (size_t)(b*HWn + iy0*Wn + ix1)*256;
    size_t i10 = (size_t)(b*HWn + iy1*Wn + ix0)*256;
    size_t i11 = (size_t)(b*HWn + iy1*Wn + ix1)*256;

    int ic0 = lane * 8;
    uint4 h0 = __ldg((const uint4*)(featH + i00 + ic0));
    uint4 h1 = __ldg((const uint4*)(featH + i01 + ic0));
    uint4 h2 = __ldg((const uint4*)(featH + i10 + ic0));
    uint4 h3 = __ldg((const uint4*)(featH + i11 + ic0));
    uint4 l0 = __ldg((const uint4*)(featL + i00 + ic0));
    uint4 l1 = __ldg((const uint4*)(featL + i01 + ic0));
    uint4 l2 = __ldg((const uint4*)(featL + i10 + ic0));
    uint4 l3 = __ldg((const uint4*)(featL + i11 + ic0));

    uint32_t pk[8];
    #pragma unroll
    for (int j = 0; j < 8; j++) {
        int wi = j >> 1;
        uint32_t a0 = (&h0.x)[wi], a1 = (&h1.x)[wi], a2 = (&h2.x)[wi], a3 = (&h3.x)[wi];
        uint32_t b0 = (&l0.x)[wi], b1 = (&l1.x)[wi], b2 = (&l2.x)[wi], b3 = (&l3.x)[wi];
        float v;
        if (j & 1) {
            v = w00*(bfhi(a0)+bfhi(b0)) + w01*(bfhi(a1)+bfhi(b1))
              + w10*(bfhi(a2)+bfhi(b2)) + w11*(bfhi(a3)+bfhi(b3));
        } else {
            v = w00*(bflo(a0)+bflo(b0)) + w01*(bflo(a1)+bflo(b1))
              + w10*(bflo(a2)+bflo(b2)) + w11*(bflo(a3)+bflo(b3));
        }
        pk[j] = packpair(v);
    }
    uint4 hv = { prmt(pk[0],pk[1],0x5410), prmt(pk[2],pk[3],0x5410),
                 prmt(pk[4],pk[5],0x5410), prmt(pk[6],pk[7],0x5410) };
    uint4 lv = { prmt(pk[0],pk[1],0x7632), prmt(pk[2],pk[3],0x7632),
                 prmt(pk[4],pk[5],0x7632), prmt(pk[6],pk[7],0x7632) };
    size_t o = (size_t)pg*Kdcn + tap*256 + ic0;
    *reinterpret_cast<uint4*>(sH + o) = hv;
    *reinterpret_cast<uint4*>(sL + o) = lv;
}

// =====================================================================
// dcn GEMM: conv-clone reading dense im2col samp rows, 2x2 64x64 tiles.
// 128 threads; grid (256, 2, 2); out fp32 [oc][NPIX] + relu.
// =====================================================================
__global__ void __launch_bounds__(128, 2)
dgemm_kernel(const bf16* __restrict__ s0H, const bf16* __restrict__ s0L,
             const bf16* __restrict__ s1H, const bf16* __restrict__ s1L,
             const bf16* __restrict__ w0H, const bf16* __restrict__ w0L,
             const bf16* __restrict__ w1H, const bf16* __restrict__ w1L,
             float* __restrict__ o0, float* __restrict__ o1)
{
    extern __shared__ __align__(128) char smem[];
    const int z = blockIdx.z;
    const bf16* sampH = z ? s1H : s0H;
    const bf16* sampL = z ? s1L : s0L;
    const bf16* wH    = z ? w1H : w0H;
    const bf16* wL    = z ? w1L : w0L;
    float* outf       = z ? o1 : o0;

    const uint32_t sbase = smem_to_u32(smem);
    const int tid  = threadIdx.x;
    const int wid  = tid >> 5, lane = tid & 31;
    const int pxb  = blockIdx.x * 128;
    const int ocbase = blockIdx.y * 128;

    const int m0 = (wid & 1) * 64;
    const int n0 = (wid >> 1) * 64;
    const int l7   = lane & 7;
    const int aR   = l7 + ((lane >> 3) & 1) * 8;
    const int bpx  = l7 + (lane >> 4) * 8;
    const int qA0  = (lane >> 4);
    const int qB0  = ((lane >> 3) & 1);
    const int swzL = (l7 >> 1) & 3;

    float acc[32][4];
    #pragma unroll
    for (int i = 0; i < 32; i++)
        #pragma unroll
        for (int j = 0; j < 4; j++) acc[i][j] = 0.f;

    auto load_chunk = [&](int stg, int cc) {
        const uint32_t su = sbase + stg * CSTG;
        {
            int row = tid;
            int sw = (row >> 1) & 3;
            const bf16* sH = wH + (size_t)(ocbase + row) * Kdcn + cc * 32;
            const bf16* sL = wL + (size_t)(ocbase + row) * Kdcn + cc * 32;
            uint32_t drow = su + row * 64;
            #pragma unroll
            for (int ch = 0; ch < 4; ch++) {
                uint32_t off = (uint32_t)((ch ^ sw) << 4);
                cpasync16(drow + CAH + off, sH + ch*8, 16);
                cpasync16(drow + CAL + off, sL + ch*8, 16);
            }
        }
        {
            int p = tid;
            size_t so = (size_t)(pxb + p)*Kdcn + cc * 32;
            int sw = (p >> 1) & 3;
            uint32_t drow = su + p * 64;
            #pragma unroll
            for (int ch = 0; ch < 4; ch++) {
                uint32_t off = (uint32_t)((ch ^ sw) << 4);
                cpasync16(drow + CBH + off, sampH + so + ch*8, 16);
                cpasync16(drow + CBL + off, sampL + so + ch*8, 16);
            }
        }
        cpcommit();
    };

    auto compute = [&](int stg) {
        const uint32_t Sb = sbase + stg*CSTG;
        #pragma unroll
        for (int ks = 0; ks < 2; ks++) {
            uint32_t qa = (uint32_t)(((ks*2 + qA0) ^ swzL) << 4);
            uint32_t qb = (uint32_t)(((ks*2 + qB0) ^ swzL) << 4);
            uint32_t bh[4][4], bl[4][4];
            #pragma unroll
            for (int nb = 0; nb < 4; nb++) {
                uint32_t bRow = (uint32_t)((n0 + nb*16 + bpx) * 64);
                ldsm4(bh[nb], Sb + CBH + bRow + qb);
                ldsm4(bl[nb], Sb + CBL + bRow + qb);
            }
            #pragma unroll
            for (int mf = 0; mf < 4; mf++) {
                uint32_t aRow = (uint32_t)((m0 + mf*16 + aR) * 64);
                uint32_t ah[4], al[4];
                ldsm4(ah, Sb + CAH + aRow + qa);
                ldsm4(al, Sb + CAL + aRow + qa);
                #pragma unroll
                for (int nb = 0; nb < 4; nb++) {
                    int ai = mf*8 + nb*2;
                    mma16816(acc[ai],     ah, bh[nb][0], bh[nb][1]);
                    mma16816(acc[ai + 1], ah, bh[nb][2], bh[nb][3]);
                    mma16816(acc[ai],     ah, bl[nb][0], bl[nb][1]);
                    mma16816(acc[ai + 1], ah, bl[nb][2], bl[nb][3]);
                    mma16816(acc[ai],     al, bh[nb][0], bh[nb][1]);
                    mma16816(acc[ai + 1], al, bh[nb][2], bh[nb][3]);
                }
            }
        }
    };

    load_chunk(0, 0);
    cpwait0();
    __syncthreads();
    for (int c = 0; c < NCHUNK; c++) {
        int cur = c & 1;
        if (c + 1 < NCHUNK) load_chunk(cur ^ 1, c + 1);
        compute(cur);
        cpwait0();
        __syncthreads();
    }

    // epilogue: fp32 [oc][NPIX], relu
    const int r  = lane >> 2;
    const int c2 = (lane & 3) * 2;
    #pragma unroll
    for (int mf = 0; mf < 4; mf++) {
        #pragma unroll
        for (int rr = 0; rr < 2; rr++) {
            int oc = ocbase + m0 + mf*16 + r + rr*8;
            #pragma unroll
            for (int nb = 0; nb < 4; nb++) {
                #pragma unroll
                for (int h = 0; h < 2; h++) {
                    float* d = acc[mf*8 + nb*2 + h];
                    int x0 = n0 + nb*16 + h*8 + c2;
                    float2 fv = { fmaxf(d[rr*2], 0.f), fmaxf(d[rr*2+1], 0.f) };
                    *reinterpret_cast<float2*>(outf + (size_t)oc*NPIX + pxb + x0) = fv;
                }
            }
        }
    }
}

// ---------------- small kernels ----------------
__global__ void __launch_bounds__(256)
conv1x1_27_kernel(const bf16* __restrict__ inH, const bf16* __restrict__ inL,
                  const float* __restrict__ wgt, const float* __restrict__ bias,
                  float* __restrict__ out)
{
    __shared__ float ws[Cn*27];
    for (int idx = threadIdx.x; idx < Cn*27; idx += 256) {
        int o = idx >> 8, ic = idx & 255;
        ws[ic*27 + o] = wgt[(size_t)o*Cn + ic];
    }
    __syncthreads();
    int p  = blockIdx.x * 256 + threadIdx.x;
    int b  = p >> 14;
    int hw = p & (HWn - 1);
    float acc[27];
    #pragma unroll
    for (int o = 0; o < 27; o++) acc[o] = 0.f;
    const uint4* ipH = reinterpret_cast<const uint4*>(inH + (size_t)p*256);
    const uint4* ipL = reinterpret_cast<const uint4*>(inL + (size_t)p*256);
    for (int g = 0; g < 32; g++) {
        uint4 h = __ldg(ipH + g), l = __ldg(ipL + g);
        float v[8];
        v[0] = bflo(h.x) + bflo(l.x); v[1] = bfhi(h.x) + bfhi(l.x);
        v[2] = bflo(h.y) + bflo(l.y); v[3] = bfhi(h.y) + bfhi(l.y);
        v[4] = bflo(h.z) + bflo(l.z); v[5] = bfhi(h.z) + bfhi(l.z);
        v[6] = bflo(h.w) + bflo(l.w); v[7] = bfhi(h.w) + bfhi(l.w);
        const float* w0 = &ws[(g*8)*27];
        #pragma unroll
        for (int j = 0; j < 8; j++)
            #pragma unroll
            for (int o = 0; o < 27; o++)
                acc[o] += v[j] * w0[j*27 + o];
    }
    #pragma unroll
    for (int o = 0; o < 27; o++)
        out[((size_t)(b*27) + o)*HWn + hw] = acc[o] + bias[o];
}

__global__ void __launch_bounds__(256)
conv1x1_cls_kernel(const float* __restrict__ in, const float* __restrict__ wgt,
                   const float* __restrict__ bias, float* __restrict__ out)
{
    __shared__ float ws[Cn*16];
    int g = blockIdx.y;
    for (int idx = threadIdx.x; idx < Cn*16; idx += 256) {
        int j = idx >> 8, ic = idx & 255;
        ws[ic*16 + j] = wgt[(size_t)(g*16 + j)*Cn + ic];
    }
    __syncthreads();
    int p  = blockIdx.x * 256 + threadIdx.x;
    int b  = p >> 14;
    int hw = p & (HWn - 1);
    float acc[16];
    #pragma unroll
    for (int j = 0; j < 16; j++) acc[j] = 0.f;
    for (int ic = 0; ic < Cn; ic++) {
        float v = __ldg(&in[(size_t)ic*NPIX + p]);
        #pragma unroll
        for (int j = 0; j < 16; j++) acc[j] += v * ws[ic*16 + j];
    }
    #pragma unroll
    for (int j = 0; j < 16; j++) {
        int oc = g*16 + j;
        out[((size_t)(b*NCn) + oc)*HWn + hw] = acc[j] + bias[oc];
    }
}

__global__ void __launch_bounds__(256)
ref_fused_kernel(const float* __restrict__ in, const float* __restrict__ wgt,
                 const float* __restrict__ bias, const float* __restrict__ off,
                 float* __restrict__ dout)
{
    __shared__ float ws[Cn*18];
    for (int idx = threadIdx.x; idx < Cn*18; idx += 256) {
        int o = idx >> 8, ic = idx & 255;
        ws[ic*18 + o] = wgt[(size_t)o*Cn + ic];
    }
    __syncthreads();
    int p  = blockIdx.x * 256 + threadIdx.x;
    int b  = p >> 14;
    int hw = p & (HWn - 1);
    float acc[18];
    #pragma unroll
    for (int o = 0; o < 18; o++) acc[o] = 0.f;
    for (int ic = 0; ic < Cn; ic++) {
        float v = __ldg(&in[(size_t)ic*NPIX + p]);
        #pragma unroll
        for (int o = 0; o < 18; o++) acc[o] += v * ws[ic*18 + o];
    }
    float refine[18];
    #pragma unroll
    for (int o = 0; o < 18; o++)
        refine[o] = acc[o] + bias[o] + off[((size_t)(b*27) + o)*HWn + hw];
    float m0 = 0.f, m1 = 0.f;
    #pragma unroll
    for (int q = 0; q < 9; q++) { m0 += refine[2*q]; m1 += refine[2*q + 1]; }
    m0 *= (1.f/9.f); m1 *= (1.f/9.f);
    float wh0 = 0.f, wh1 = 0.f;
    #pragma unroll
    for (int q = 0; q < 9; q++) {
        wh0 = fmaxf(wh0, fabsf(refine[2*q]     + m0));
        wh1 = fmaxf(wh1, fabsf(refine[2*q + 1] + m1));
    }
    const size_t OUT_WH  = (size_t)Bn*NCn*HWn;
    const size_t OUT_REG = OUT_WH + (size_t)Bn*2*HWn;
    dout[OUT_WH  + ((size_t)(b*2) + 0)*HWn + hw] = wh0;
    dout[OUT_WH  + ((size_t)(b*2) + 1)*HWn + hw] = wh1;
    dout[OUT_REG + ((size_t)(b*2) + 0)*HWn + hw] = m0;
    dout[OUT_REG + ((size_t)(b*2) + 1)*HWn + hw] = m1;
}

// =====================================================================
extern "C" void kernel_launch(void* const* d_in, const int* in_sizes, int n_in,
                              void* d_out, int out_size)
{
    const float* x = (const float*)d_in[0];
    WPtrs wp;
    wp.w[0] = (const float*)d_in[1];   // cls_w0
    wp.w[1] = (const float*)d_in[5];   // cls_w1
    wp.w[2] = (const float*)d_in[9];   // cls_w2
    wp.w[3] = (const float*)d_in[3];   // reg_w0
    wp.w[4] = (const float*)d_in[7];   // reg_w1
    wp.w[5] = (const float*)d_in[11];  // reg_w2
    wp.w[6] = (const float*)d_in[13];  // init_conv_w
    wp.w[7] = (const float*)d_in[17];  // dcn_cls_w
    wp.w[8] = (const float*)d_in[20];  // dcn_ref_w
    const float* cls_b0      = (const float*)d_in[2];
    const float* cls_b1      = (const float*)d_in[6];
    const float* cls_b2      = (const float*)d_in[10];
    const float* reg_b0      = (const float*)d_in[4];
    const float* reg_b1      = (const float*)d_in[8];
    const float* reg_b2      = (const float*)d_in[12];
    const float* init_conv_b = (const float*)d_in[14];
    const float* init_out_w  = (const float*)d_in[15];
    const float* init_out_b  = (const float*)d_in[16];
    const float* cls_out_w   = (const float*)d_in[18];
    const float* cls_out_b   = (const float*)d_in[19];
    const float* ref_out_w   = (const float*)d_in[21];
    const float* ref_out_b   = (const float*)d_in[22];
    float* out = (float*)d_out;

    bf16 *xH,*xL,*aH,*aL,*bH,*bL,*cH,*cL,*dH,*dL,*clsH,*clsL,*ptsH,*ptsL,*wH,*wL;
    bf16 *s0H,*s0L,*s1H,*s1L;
    float *off, *dcn0, *dcn1;
    cudaGetSymbolAddress((void**)&xH,  g_xH);   cudaGetSymbolAddress((void**)&xL,  g_xL);
    cudaGetSymbolAddress((void**)&aH,  g_aH);   cudaGetSymbolAddress((void**)&aL,  g_aL);
    cudaGetSymbolAddress((void**)&bH,  g_bH);   cudaGetSymbolAddress((void**)&bL,  g_bL);
    cudaGetSymbolAddress((void**)&cH,  g_cH);   cudaGetSymbolAddress((void**)&cL,  g_cL);
    cudaGetSymbolAddress((void**)&dH,  g_dH);   cudaGetSymbolAddress((void**)&dL,  g_dL);
    cudaGetSymbolAddress((void**)&clsH, g_clsH); cudaGetSymbolAddress((void**)&clsL, g_clsL);
    cudaGetSymbolAddress((void**)&ptsH, g_ptsH); cudaGetSymbolAddress((void**)&ptsL, g_ptsL);
    cudaGetSymbolAddress((void**)&wH,  g_wH);   cudaGetSymbolAddress((void**)&wL,  g_wL);
    cudaGetSymbolAddress((void**)&s0H, g_s0H);  cudaGetSymbolAddress((void**)&s0L, g_s0L);
    cudaGetSymbolAddress((void**)&s1H, g_s1H);  cudaGetSymbolAddress((void**)&s1L, g_s1L);
    cudaGetSymbolAddress((void**)&off, g_off);
    cudaGetSymbolAddress((void**)&dcn0, g_dcn0);
    cudaGetSymbolAddress((void**)&dcn1, g_dcn1);

    cudaFuncSetAttribute(conv_kernel,  cudaFuncAttributeMaxDynamicSharedMemorySize, CONV_SMEM);
    cudaFuncSetAttribute(dgemm_kernel, cudaFuncAttributeMaxDynamicSharedMemorySize, CONV_SMEM);

    prep_kernel<<<(PKQ + 9*WSZ)/256, 256>>>(x, wp, xH, xL, wH, wL);

    auto WH = [&](int l) { return (const bf16*)(wH + (size_t)l*WSZ); };
    auto WL = [&](int l) { return (const bf16*)(wL + (size_t)l*WSZ); };

    // dual-conv towers
    {
        ConvJob a{xH, xL, WH(0), WL(0), cls_b0, aH, aL};
        ConvJob b{xH, xL, WH(3), WL(3), reg_b0, cH, cL};
        conv_kernel<<<dim3(256,2,2), 128, CONV_SMEM>>>(a, b);
    }
    {
        ConvJob a{aH, aL, WH(1), WL(1), cls_b1, bH, bL};
        ConvJob b{cH, cL, WH(4), WL(4), reg_b1, dH, dL};
        conv_kernel<<<dim3(256,2,2), 128, CONV_SMEM>>>(a, b);
    }
    {
        ConvJob a{bH, bL, WH(2), WL(2), cls_b2, clsH, clsL};
        ConvJob b{dH, dL, WH(5), WL(5), reg_b2, ptsH, ptsL};
        conv_kernel<<<dim3(256,2,2), 128, CONV_SMEM>>>(a, b);
    }
    // init conv (single job)
    {
        ConvJob a{ptsH, ptsL, WH(6), WL(6), init_conv_b, aH, aL};
        conv_kernel<<<dim3(256,2,1), 128, CONV_SMEM>>>(a, a);
    }
    conv1x1_27_kernel<<<128, 256>>>(aH, aL, init_out_w, init_out_b, off);

    // dcn: standalone dual gather -> dual conv-clone GEMM
    gather_kernel<<<dim3(9*NPIX/8, 1, 2), 256>>>(clsH, clsL, ptsH, ptsL, off,
                                                 s0H, s0L, s1H, s1L);
    dgemm_kernel<<<dim3(256, 2, 2), 128, CONV_SMEM>>>(s0H, s0L, s1H, s1L,
                                                      WH(7), WL(7), WH(8), WL(8),
                                                      dcn0, dcn1);

    conv1x1_cls_kernel<<<dim3(128, 5), 256>>>(dcn0, cls_out_w, cls_out_b, out);
    ref_fused_kernel<<<128, 256>>>(dcn1, ref_out_w, ref_out_b, off, out);
}

// round 17
// speedup vs baseline: 1.2891x; 1.2891x over previous
#include <cuda_runtime.h>
#include <cuda_bf16.h>
#include <math.h>
#include <stdint.h>

#define Cn   256
#define Hn   128
#define Wn   128
#define Bn   2
#define HWn  (Hn*Wn)        // 16384
#define NPIX (Bn*HWn)       // 32768
#define NCn  80
#define Kdcn 2304
#define WSZ  (Cn*Kdcn)      // 589824 weights per layer
#define NCHUNK 72
#define NELEM (Bn*Cn*HWn)   // 8388608
#define PKQ  (NELEM/4)

// GEMM stage: A hi/lo planes 128oc x 64B, B hi/lo planes 128px x 64B
#define CAH 0
#define CAL 8192
#define CBH 16384
#define CBL 24576
#define CSTG 32768
#define CONV_SMEM (2*CSTG)            // 65536

typedef __nv_bfloat16 bf16;

__device__ __forceinline__ uint32_t smem_to_u32(const void* p) {
    uint32_t a;
    asm("{ .reg .u64 t; cvta.to.shared.u64 t, %1; cvt.u32.u64 %0, t; }" : "=r"(a) : "l"(p));
    return a;
}
__device__ __forceinline__ void cpasync16(uint32_t dst, const void* src, uint32_t srcsz) {
    asm volatile("cp.async.cg.shared.global [%0], [%1], 16, %2;"
        :: "r"(dst), "l"(src), "r"(srcsz) : "memory");
}
__device__ __forceinline__ void cpcommit() {
    asm volatile("cp.async.commit_group;" ::: "memory");
}
__device__ __forceinline__ void cpwait0() {
    asm volatile("cp.async.wait_group 0;" ::: "memory");
}
__device__ __forceinline__ void ldsm4(uint32_t r[4], uint32_t addr) {
    asm volatile("ldmatrix.sync.aligned.m8n8.x4.shared.b16 {%0,%1,%2,%3}, [%4];"
        : "=r"(r[0]), "=r"(r[1]), "=r"(r[2]), "=r"(r[3]) : "r"(addr));
}
__device__ __forceinline__ void mma16816(float d[4], const uint32_t a[4],
                                         uint32_t b0, uint32_t b1) {
    asm volatile(
        "mma.sync.aligned.m16n8k16.row.col.f32.bf16.bf16.f32 "
        "{%0,%1,%2,%3}, {%4,%5,%6,%7}, {%8,%9}, {%0,%1,%2,%3};"
        : "+f"(d[0]), "+f"(d[1]), "+f"(d[2]), "+f"(d[3])
        : "r"(a[0]), "r"(a[1]), "r"(a[2]), "r"(a[3]), "r"(b0), "r"(b1));
}
__device__ __forceinline__ uint32_t prmt(uint32_t a, uint32_t b, uint32_t sel) {
    uint32_t d; asm("prmt.b32 %0,%1,%2,%3;" : "=r"(d) : "r"(a), "r"(b), "r"(sel));
    return d;
}
__device__ __forceinline__ void stcs16(void* dst, uint4 v) {
    asm volatile("st.global.cs.v4.b32 [%0], {%1,%2,%3,%4};"
        :: "l"(dst), "r"(v.x), "r"(v.y), "r"(v.z), "r"(v.w) : "memory");
}
// packed word: low16 = bf16(v), high16 = bf16(v - bf16(v))
__device__ __forceinline__ uint32_t packpair(float v) {
    bf16 h = __float2bfloat16(v);
    float hf = __bfloat162float(h);
    bf16 l = __float2bfloat16(v - hf);
    uint16_t hb = *reinterpret_cast<uint16_t*>(&h);
    uint16_t lb = *reinterpret_cast<uint16_t*>(&l);
    return (uint32_t)hb | ((uint32_t)lb << 16);
}
__device__ __forceinline__ float bflo(uint32_t w) { return __int_as_float(w << 16); }
__device__ __forceinline__ float bfhi(uint32_t w) { return __int_as_float(w & 0xFFFF0000u); }

// ---------------- scratch: hi/lo bf16 plane maps, channel-last [pix][256] ----------------
__device__ __align__(16) bf16 g_xH [NELEM];
__device__ __align__(16) bf16 g_xL [NELEM];
__device__ __align__(16) bf16 g_aH [NELEM];
__device__ __align__(16) bf16 g_aL [NELEM];
__device__ __align__(16) bf16 g_bH [NELEM];
__device__ __align__(16) bf16 g_bL [NELEM];
__device__ __align__(16) bf16 g_cH [NELEM];
__device__ __align__(16) bf16 g_cL [NELEM];
__device__ __align__(16) bf16 g_dH [NELEM];
__device__ __align__(16) bf16 g_dL [NELEM];
__device__ __align__(16) bf16 g_clsH[NELEM];
__device__ __align__(16) bf16 g_clsL[NELEM];
__device__ __align__(16) bf16 g_ptsH[NELEM];
__device__ __align__(16) bf16 g_ptsL[NELEM];
__device__ float g_off [Bn*27*HWn];
__device__ float g_dcn0[(size_t)Cn*NPIX];
__device__ float g_dcn1[(size_t)Cn*NPIX];
__device__ __align__(16) bf16 g_wH[9*WSZ];
__device__ __align__(16) bf16 g_wL[9*WSZ];
// im2col sampled tensors for the two dcns: [px][2304] hi/lo planes
__device__ __align__(16) bf16 g_s0H[(size_t)NPIX*Kdcn];
__device__ __align__(16) bf16 g_s0L[(size_t)NPIX*Kdcn];
__device__ __align__(16) bf16 g_s1H[(size_t)NPIX*Kdcn];
__device__ __align__(16) bf16 g_s1L[(size_t)NPIX*Kdcn];

struct WPtrs { const float* w[9]; };

// ---------------- prep: plane-split x + all 9 weights (one launch) ----------------
__global__ void __launch_bounds__(256)
prep_kernel(const float* __restrict__ x, WPtrs wp,
            bf16* __restrict__ xH, bf16* __restrict__ xL,
            bf16* __restrict__ wH, bf16* __restrict__ wL)
{
    int gid = blockIdx.x * 256 + threadIdx.x;
    if (gid < PKQ) {
        int hw  = gid & (HWn - 1);
        int rem = gid >> 14;
        int cg  = rem & 63;
        int b   = rem >> 6;
        const float* src = x + ((size_t)(b*Cn + cg*4))*HWn + hw;
        uint32_t pk0 = packpair(__ldg(src));
        uint32_t pk1 = packpair(__ldg(src + HWn));
        uint32_t pk2 = packpair(__ldg(src + 2*HWn));
        uint32_t pk3 = packpair(__ldg(src + 3*HWn));
        uint2 hv = { prmt(pk0, pk1, 0x5410), prmt(pk2, pk3, 0x5410) };
        uint2 lv = { prmt(pk0, pk1, 0x7632), prmt(pk2, pk3, 0x7632) };
        size_t o = (size_t)(b*HWn + hw)*256 + cg*4;
        *reinterpret_cast<uint2*>(xH + o) = hv;
        *reinterpret_cast<uint2*>(xL + o) = lv;
    } else {
        int i = gid - PKQ;                 // < 9*WSZ
        int l = i / WSZ, r = i - l*WSZ;
        int oc = r / Kdcn, kp = r - oc*Kdcn;
        int tap = kp >> 8, ic = kp & 255;
        float v = wp.w[l][((size_t)oc*256 + ic)*9 + tap];
        bf16 h = __float2bfloat16(v);
        wH[i] = h;
        wL[i] = __float2bfloat16(v - __bfloat162float(h));
    }
}

// =====================================================================
// Dual-job conv3x3, 3-plane MMA (measured-best r15 config: 256 thr,
// 4m x 2n warps of 32x64, 2 CTA/SM). Grid (256, 2, 2).
// =====================================================================
struct ConvJob {
    const bf16* inH; const bf16* inL;
    const bf16* wH;  const bf16* wL;
    const float* bias;
    bf16* outH; bf16* outL;
};

__global__ void __launch_bounds__(256, 2)
conv_kernel(ConvJob j0, ConvJob j1)
{
    extern __shared__ __align__(128) char smem[];
    const ConvJob J = blockIdx.z ? j1 : j0;
    const uint32_t sbase = smem_to_u32(smem);
    const int tid  = threadIdx.x;
    const int wid  = tid >> 5, lane = tid & 31;
    const int nblk = blockIdx.x;
    const int b = nblk >> 7, y = nblk & 127;
    const int ocbase = blockIdx.y * 128;

    const int m0 = (wid & 3) * 32;
    const int n0 = (wid >> 2) * 64;
    const int l7   = lane & 7;
    const int aR   = l7 + ((lane >> 3) & 1) * 8;
    const int bpx  = l7 + (lane >> 4) * 8;
    const int qA0  = (lane >> 4);
    const int qB0  = ((lane >> 3) & 1);
    const int swzL = (l7 >> 1) & 3;

    float acc[16][4];
    #pragma unroll
    for (int i = 0; i < 16; i++)
        #pragma unroll
        for (int j = 0; j < 4; j++) acc[i][j] = 0.f;

    auto load_chunk = [&](int stg, int cc) {
        const uint32_t su = sbase + stg * CSTG;
        {
            int row = tid >> 1, seg = tid & 1;
            int sw = (row >> 1) & 3;
            const bf16* sH = J.wH + (size_t)(ocbase + row) * Kdcn + cc * 32;
            const bf16* sL = J.wL + (size_t)(ocbase + row) * Kdcn + cc * 32;
            uint32_t drow = su + row * 64;
            #pragma unroll
            for (int i = 0; i < 2; i++) {
                int ch = seg*2 + i;
                uint32_t off = (uint32_t)((ch ^ sw) << 4);
                cpasync16(drow + CAH + off, sH + ch*8, 16);
                cpasync16(drow + CAL + off, sL + ch*8, 16);
            }
        }
        const int tap = cc >> 3;
        const int ic0 = (cc & 7) * 32;
        const int ky = tap / 3 - 1, kx = tap % 3 - 1;
        int p = tid >> 1, seg = tid & 1;
        int yy = y + ky, xx = p + kx;
        bool ok = (yy >= 0 && yy < Hn && xx >= 0 && xx < Wn);
        size_t so = (size_t)(b*HWn + yy*Wn + xx)*256 + ic0;
        uint32_t srcsz = ok ? 16u : 0u;
        int sw = (p >> 1) & 3;
        uint32_t drow = su + p * 64;
        #pragma unroll
        for (int i = 0; i < 2; i++) {
            int ch = seg*2 + i;
            uint32_t off = (uint32_t)((ch ^ sw) << 4);
            cpasync16(drow + CBH + off, J.inH + so + ch*8, srcsz);
            cpasync16(drow + CBL + off, J.inL + so + ch*8, srcsz);
        }
        cpcommit();
    };

    auto compute = [&](int stg) {
        const uint32_t Sb = sbase + stg*CSTG;
        const uint32_t aRow = (uint32_t)((m0 + aR) * 64);
        const uint32_t bRow = (uint32_t)((n0 + bpx) * 64);
        #pragma unroll
        for (int ks = 0; ks < 2; ks++) {
            uint32_t qa = (uint32_t)(((ks*2 + qA0) ^ swzL) << 4);
            uint32_t qb = (uint32_t)(((ks*2 + qB0) ^ swzL) << 4);
            uint32_t ah[2][4], al[2][4];
            ldsm4(ah[0], Sb + CAH + aRow + qa);
            ldsm4(ah[1], Sb + CAH + aRow + 16*64 + qa);
            ldsm4(al[0], Sb + CAL + aRow + qa);
            ldsm4(al[1], Sb + CAL + aRow + 16*64 + qa);
            #pragma unroll
            for (int nb = 0; nb < 4; nb++) {
                uint32_t bh[4], bl[4];
                ldsm4(bh, Sb + CBH + bRow + (uint32_t)(nb*16*64) + qb);
                ldsm4(bl, Sb + CBL + bRow + (uint32_t)(nb*16*64) + qb);
                #pragma unroll
                for (int mt = 0; mt < 2; mt++) {
                    mma16816(acc[mt*8 + 2*nb],     ah[mt], bh[0], bh[1]);
                    mma16816(acc[mt*8 + 2*nb + 1], ah[mt], bh[2], bh[3]);
                    mma16816(acc[mt*8 + 2*nb],     ah[mt], bl[0], bl[1]);
                    mma16816(acc[mt*8 + 2*nb + 1], ah[mt], bl[2], bl[3]);
                    mma16816(acc[mt*8 + 2*nb],     al[mt], bh[0], bh[1]);
                    mma16816(acc[mt*8 + 2*nb + 1], al[mt], bh[2], bh[3]);
                }
            }
        }
    };

    load_chunk(0, 0);
    cpwait0();
    __syncthreads();
    for (int c = 0; c < NCHUNK; c++) {
        int cur = c & 1;
        if (c + 1 < NCHUNK) load_chunk(cur ^ 1, c + 1);
        compute(cur);
        cpwait0();
        __syncthreads();
    }

    const int r  = lane >> 2;
    const int c2 = (lane & 3) * 2;
    __syncthreads();
    uint32_t* st = reinterpret_cast<uint32_t*>(smem);
    #pragma unroll
    for (int mt = 0; mt < 2; mt++) {
        #pragma unroll
        for (int rr = 0; rr < 2; rr++) {
            int oc_l = m0 + mt*16 + r + rr*8;
            float bv = __ldg(&J.bias[ocbase + oc_l]);
            #pragma unroll
            for (int nt = 0; nt < 8; nt++) {
                float* d = acc[mt*8 + nt];
                int x0 = n0 + nt*8 + c2;
                float v0 = fmaxf(d[rr*2]   + bv, 0.f);
                float v1 = fmaxf(d[rr*2+1] + bv, 0.f);
                st[x0*128     + (oc_l ^ ((x0     & 7) << 2))] = packpair(v0);
                st[(x0+1)*128 + (oc_l ^ (((x0+1) & 7) << 2))] = packpair(v1);
            }
        }
    }
    __syncthreads();
    {
        int p = tid >> 1, half = tid & 1;
        int sw = (p & 7) << 2;
        size_t o = (size_t)(b*HWn + y*Wn + p)*256 + ocbase + half*64;
        #pragma unroll
        for (int j4 = 0; j4 < 16; j4++) {
            int w = half*64 + j4*4;
            uint4 v = *reinterpret_cast<const uint4*>(st + p*128 + (w ^ sw));
            uint2 hv = { prmt(v.x, v.y, 0x5410), prmt(v.z, v.w, 0x5410) };
            uint2 lv = { prmt(v.x, v.y, 0x7632), prmt(v.z, v.w, 0x7632) };
            *reinterpret_cast<uint2*>(J.outH + o + j4*4) = hv;
            *reinterpret_cast<uint2*>(J.outL + o + j4*4) = lv;
        }
    }
}

// =====================================================================
// Standalone dual-job bilinear gather -> im2col planes samp[px][2304].
// Warp = one (tap, pixel); lane = 8-channel group.
// grid (9*NPIX/8 = 36864, 1, 2), 256 threads.
// samp writes use st.global.cs (streaming) to keep feat planes L2-resident.
// =====================================================================
__global__ void __launch_bounds__(256)
gather_kernel(const bf16* __restrict__ f0H, const bf16* __restrict__ f0L,
              const bf16* __restrict__ f1H, const bf16* __restrict__ f1L,
              const float* __restrict__ off,
              bf16* __restrict__ s0H, bf16* __restrict__ s0L,
              bf16* __restrict__ s1H, bf16* __restrict__ s1L)
{
    const int z = blockIdx.z;
    const bf16* featH = z ? f1H : f0H;
    const bf16* featL = z ? f1L : f0L;
    bf16* sH = z ? s1H : s0H;
    bf16* sL = z ? s1L : s0L;
    const bool use_mask = (z == 0);

    int gw   = blockIdx.x * 8 + (threadIdx.x >> 5);
    int lane = threadIdx.x & 31;
    int tap  = gw >> 15;
    int pg   = gw & (NPIX - 1);
    int b  = pg >> 14;
    int hw = pg & (HWn - 1);
    int y  = hw >> 7, x = hw & 127;
    int ky = tap / 3 - 1, kx = tap % 3 - 1;

    const float* offb = off + (size_t)b*27*HWn + hw;
    float offy = __ldg(offb + (size_t)(2*tap)*HWn);
    float offx = __ldg(offb + (size_t)(2*tap + 1)*HWn);
    float py = (float)(y + ky) + offy;
    float px = (float)(x + kx) + offx;
    float fy0 = floorf(py), fx0 = floorf(px);
    float ly = py - fy0, lx = px - fx0;
    bool vy0 = (fy0 >= 0.f)       && (fy0 <= 127.f);
    bool vy1 = (fy0 + 1.f >= 0.f) && (fy0 + 1.f <= 127.f);
    bool vx0 = (fx0 >= 0.f)       && (fx0 <= 127.f);
    bool vx1 = (fx0 + 1.f >= 0.f) && (fx0 + 1.f <= 127.f);
    float w00 = (1.f-ly)*(1.f-lx) * ((vy0 && vx0) ? 1.f : 0.f);
    float w01 = (1.f-ly)*lx       * ((vy0 && vx1) ? 1.f : 0.f);
    float w10 = ly*(1.f-lx)       * ((vy1 && vx0) ? 1.f : 0.f);
    float w11 = ly*lx             * ((vy1 && vx1) ? 1.f : 0.f);
    if (use_mask) {
        float m = __ldg(offb + (size_t)(18 + tap)*HWn);
        w00 *= m; w01 *= m; w10 *= m; w11 *= m;
    }
    int iy0 = min(max((int)fy0,     0), Hn-1);
    int iy1 = min(max((int)fy0 + 1, 0), Hn-1);
    int ix0 = min(max((int)fx0,     0), Wn-1);
    int ix1 = min(max((int)fx0 + 1, 0), Wn-1);
    size_t i00 = (size_t)(b*HWn + iy0*Wn + ix0)*256;
    size_t i01 = (size_t)(b*HWn + iy0*Wn + ix1)*256;
    size_t i10 = (size_t)(b*HWn + iy1*Wn + ix0)*256;
    size_t i11 = (size_t)(b*HWn + iy1*Wn + ix1)*256;

    int ic0 = lane * 8;
    uint4 h0 = __ldg((const uint4*)(featH + i00 + ic0));
    uint4 h1 = __ldg((const uint4*)(featH + i01 + ic0));
    uint4 h2 = __ldg((const uint4*)(featH + i10 + ic0));
    uint4 h3 = __ldg((const uint4*)(featH + i11 + ic0));
    uint4 l0 = __ldg((const uint4*)(featL + i00 + ic0));
    uint4 l1 = __ldg((const uint4*)(featL + i01 + ic0));
    uint4 l2 = __ldg((const uint4*)(featL + i10 + ic0));
    uint4 l3 = __ldg((const uint4*)(featL + i11 + ic0));

    uint32_t pk[8];
    #pragma unroll
    for (int j = 0; j < 8; j++) {
        int wi = j >> 1;
        uint32_t a0 = (&h0.x)[wi], a1 = (&h1.x)[wi], a2 = (&h2.x)[wi], a3 = (&h3.x)[wi];
        uint32_t b0 = (&l0.x)[wi], b1 = (&l1.x)[wi], b2 = (&l2.x)[wi], b3 = (&l3.x)[wi];
        float v;
        if (j & 1) {
            v = w00*(bfhi(a0)+bfhi(b0)) + w01*(bfhi(a1)+bfhi(b1))
              + w10*(bfhi(a2)+bfhi(b2)) + w11*(bfhi(a3)+bfhi(b3));
        } else {
            v = w00*(bflo(a0)+bflo(b0)) + w01*(bflo(a1)+bflo(b1))
              + w10*(bflo(a2)+bflo(b2)) + w11*(bflo(a3)+bflo(b3));
        }
        pk[j] = packpair(v);
    }
    uint4 hv = { prmt(pk[0],pk[1],0x5410), prmt(pk[2],pk[3],0x5410),
                 prmt(pk[4],pk[5],0x5410), prmt(pk[6],pk[7],0x5410) };
    uint4 lv = { prmt(pk[0],pk[1],0x7632), prmt(pk[2],pk[3],0x7632),
                 prmt(pk[4],pk[5],0x7632), prmt(pk[6],pk[7],0x7632) };
    size_t o = (size_t)pg*Kdcn + tap*256 + ic0;
    stcs16(sH + o, hv);
    stcs16(sL + o, lv);
}

// =====================================================================
// dcn GEMM: conv-clone reading dense im2col samp rows. Dual-job via z.
// D[128oc][128px]; grid (256, 2, 2); out fp32 [oc][NPIX] + relu.
// =====================================================================
__global__ void __launch_bounds__(256, 2)
dgemm_kernel(const bf16* __restrict__ s0H, const bf16* __restrict__ s0L,
             const bf16* __restrict__ s1H, const bf16* __restrict__ s1L,
             const bf16* __restrict__ w0H, const bf16* __restrict__ w0L,
             const bf16* __restrict__ w1H, const bf16* __restrict__ w1L,
             float* __restrict__ o0, float* __restrict__ o1)
{
    extern __shared__ __align__(128) char smem[];
    const int z = blockIdx.z;
    const bf16* sampH = z ? s1H : s0H;
    const bf16* sampL = z ? s1L : s0L;
    const bf16* wH    = z ? w1H : w0H;
    const bf16* wL    = z ? w1L : w0L;
    float* outf       = z ? o1 : o0;

    const uint32_t sbase = smem_to_u32(smem);
    const int tid  = threadIdx.x;
    const int wid  = tid >> 5, lane = tid & 31;
    const int pxb  = blockIdx.x * 128;
    const int ocbase = blockIdx.y * 128;

    const int m0 = (wid & 3) * 32;
    const int n0 = (wid >> 2) * 64;
    const int l7   = lane & 7;
    const int aR   = l7 + ((lane >> 3) & 1) * 8;
    const int bpx  = l7 + (lane >> 4) * 8;
    const int qA0  = (lane >> 4);
    const int qB0  = ((lane >> 3) & 1);
    const int swzL = (l7 >> 1) & 3;

    float acc[16][4];
    #pragma unroll
    for (int i = 0; i < 16; i++)
        #pragma unroll
        for (int j = 0; j < 4; j++) acc[i][j] = 0.f;

    auto load_chunk = [&](int stg, int cc) {
        const uint32_t su = sbase + stg * CSTG;
        int row = tid >> 1, seg = tid & 1;
        {
            int sw = (row >> 1) & 3;
            const bf16* sH = wH + (size_t)(ocbase + row) * Kdcn + cc * 32;
            const bf16* sL = wL + (size_t)(ocbase + row) * Kdcn + cc * 32;
            uint32_t drow = su + row * 64;
            #pragma unroll
            for (int i = 0; i < 2; i++) {
                int ch = seg*2 + i;
                uint32_t off = (uint32_t)((ch ^ sw) << 4);
                cpasync16(drow + CAH + off, sH + ch*8, 16);
                cpasync16(drow + CAL + off, sL + ch*8, 16);
            }
        }
        {
            int p = row;
            size_t so = (size_t)(pxb + p)*Kdcn + cc * 32;
            int sw = (p >> 1) & 3;
            uint32_t drow = su + p * 64;
            #pragma unroll
            for (int i = 0; i < 2; i++) {
                int ch = seg*2 + i;
                uint32_t off = (uint32_t)((ch ^ sw) << 4);
                cpasync16(drow + CBH + off, sampH + so + ch*8, 16);
                cpasync16(drow + CBL + off, sampL + so + ch*8, 16);
            }
        }
        cpcommit();
    };

    auto compute = [&](int stg) {
        const uint32_t Sb = sbase + stg*CSTG;
        const uint32_t aRow = (uint32_t)((m0 + aR) * 64);
        const uint32_t bRow = (uint32_t)((n0 + bpx) * 64);
        #pragma unroll
        for (int ks = 0; ks < 2; ks++) {
            uint32_t qa = (uint32_t)(((ks*2 + qA0) ^ swzL) << 4);
            uint32_t qb = (uint32_t)(((ks*2 + qB0) ^ swzL) << 4);
            uint32_t ah[2][4], al[2][4];
            ldsm4(ah[0], Sb + CAH + aRow + qa);
            ldsm4(ah[1], Sb + CAH + aRow + 16*64 + qa);
            ldsm4(al[0], Sb + CAL + aRow + qa);
            ldsm4(al[1], Sb + CAL + aRow + 16*64 + qa);
            #pragma unroll
            for (int nb = 0; nb < 4; nb++) {
                uint32_t bh[4], bl[4];
                ldsm4(bh, Sb + CBH + bRow + (uint32_t)(nb*16*64) + qb);
                ldsm4(bl, Sb + CBL + bRow + (uint32_t)(nb*16*64) + qb);
                #pragma unroll
                for (int mt = 0; mt < 2; mt++) {
                    mma16816(acc[mt*8 + 2*nb],     ah[mt], bh[0], bh[1]);
                    mma16816(acc[mt*8 + 2*nb + 1], ah[mt], bh[2], bh[3]);
                    mma16816(acc[mt*8 + 2*nb],     ah[mt], bl[0], bl[1]);
                    mma16816(acc[mt*8 + 2*nb + 1], ah[mt], bl[2], bl[3]);
                    mma16816(acc[mt*8 + 2*nb],     al[mt], bh[0], bh[1]);
                    mma16816(acc[mt*8 + 2*nb + 1], al[mt], bh[2], bh[3]);
                }
            }
        }
    };

    load_chunk(0, 0);
    cpwait0();
    __syncthreads();
    for (int c = 0; c < NCHUNK; c++) {
        int cur = c & 1;
        if (c + 1 < NCHUNK) load_chunk(cur ^ 1, c + 1);
        compute(cur);
        cpwait0();
        __syncthreads();
    }

    const int r  = lane >> 2;
    const int c2 = (lane & 3) * 2;
    #pragma unroll
    for (int mt = 0; mt < 2; mt++) {
        #pragma unroll
        for (int rr = 0; rr < 2; rr++) {
            int oc = ocbase + m0 + mt*16 + r + rr*8;
            #pragma unroll
            for (int nt = 0; nt < 8; nt++) {
                float* d = acc[mt*8 + nt];
                int x0 = n0 + nt*8 + c2;
                float2 fv = { fmaxf(d[rr*2], 0.f), fmaxf(d[rr*2+1], 0.f) };
                *reinterpret_cast<float2*>(outf + (size_t)oc*NPIX + pxb + x0) = fv;
            }
        }
    }
}

// ---------------- small kernels ----------------
__global__ void __launch_bounds__(256)
conv1x1_27_kernel(const bf16* __restrict__ inH, const bf16* __restrict__ inL,
                  const float* __restrict__ wgt, const float* __restrict__ bias,
                  float* __restrict__ out)
{
    __shared__ float ws[Cn*27];
    for (int idx = threadIdx.x; idx < Cn*27; idx += 256) {
        int o = idx >> 8, ic = idx & 255;
        ws[ic*27 + o] = wgt[(size_t)o*Cn + ic];
    }
    __syncthreads();
    int p  = blockIdx.x * 256 + threadIdx.x;
    int b  = p >> 14;
    int hw = p & (HWn - 1);
    float acc[27];
    #pragma unroll
    for (int o = 0; o < 27; o++) acc[o] = 0.f;
    const uint4* ipH = reinterpret_cast<const uint4*>(inH + (size_t)p*256);
    const uint4* ipL = reinterpret_cast<const uint4*>(inL + (size_t)p*256);
    for (int g = 0; g < 32; g++) {
        uint4 h = __ldg(ipH + g), l = __ldg(ipL + g);
        float v[8];
        v[0] = bflo(h.x) + bflo(l.x); v[1] = bfhi(h.x) + bfhi(l.x);
        v[2] = bflo(h.y) + bflo(l.y); v[3] = bfhi(h.y) + bfhi(l.y);
        v[4] = bflo(h.z) + bflo(l.z); v[5] = bfhi(h.z) + bfhi(l.z);
        v[6] = bflo(h.w) + bflo(l.w); v[7] = bfhi(h.w) + bfhi(l.w);
        const float* w0 = &ws[(g*8)*27];
        #pragma unroll
        for (int j = 0; j < 8; j++)
            #pragma unroll
            for (int o = 0; o < 27; o++)
                acc[o] += v[j] * w0[j*27 + o];
    }
    #pragma unroll
    for (int o = 0; o < 27; o++)
        out[((size_t)(b*27) + o)*HWn + hw] = acc[o] + bias[o];
}

__global__ void __launch_bounds__(256)
conv1x1_cls_kernel(const float* __restrict__ in, const float* __restrict__ wgt,
                   const float* __restrict__ bias, float* __restrict__ out)
{
    __shared__ float ws[Cn*16];
    int g = blockIdx.y;
    for (int idx = threadIdx.x; idx < Cn*16; idx += 256) {
        int j = idx >> 8, ic = idx & 255;
        ws[ic*16 + j] = wgt[(size_t)(g*16 + j)*Cn + ic];
    }
    __syncthreads();
    int p  = blockIdx.x * 256 + threadIdx.x;
    int b  = p >> 14;
    int hw = p & (HWn - 1);
    float acc[16];
    #pragma unroll
    for (int j = 0; j < 16; j++) acc[j] = 0.f;
    for (int ic = 0; ic < Cn; ic++) {
        float v = __ldg(&in[(size_t)ic*NPIX + p]);
        #pragma unroll
        for (int j = 0; j < 16; j++) acc[j] += v * ws[ic*16 + j];
    }
    #pragma unroll
    for (int j = 0; j < 16; j++) {
        int oc = g*16 + j;
        out[((size_t)(b*NCn) + oc)*HWn + hw] = acc[j] + bias[oc];
    }
}

__global__ void __launch_bounds__(256)
ref_fused_kernel(const float* __restrict__ in, const float* __restrict__ wgt,
                 const float* __restrict__ bias, const float* __restrict__ off,
                 float* __restrict__ dout)
{
    __shared__ float ws[Cn*18];
    for (int idx = threadIdx.x; idx < Cn*18; idx += 256) {
        int o = idx >> 8, ic = idx & 255;
        ws[ic*18 + o] = wgt[(size_t)o*Cn + ic];
    }
    __syncthreads();
    int p  = blockIdx.x * 256 + threadIdx.x;
    int b  = p >> 14;
    int hw = p & (HWn - 1);
    float acc[18];
    #pragma unroll
    for (int o = 0; o < 18; o++) acc[o] = 0.f;
    for (int ic = 0; ic < Cn; ic++) {
        float v = __ldg(&in[(size_t)ic*NPIX + p]);
        #pragma unroll
        for (int o = 0; o < 18; o++) acc[o] += v * ws[ic*18 + o];
    }
    float refine[18];
    #pragma unroll
    for (int o = 0; o < 18; o++)
        refine[o] = acc[o] + bias[o] + off[((size_t)(b*27) + o)*HWn + hw];
    float m0 = 0.f, m1 = 0.f;
    #pragma unroll
    for (int q = 0; q < 9; q++) { m0 += refine[2*q]; m1 += refine[2*q + 1]; }
    m0 *= (1.f/9.f); m1 *= (1.f/9.f);
    float wh0 = 0.f, wh1 = 0.f;
    #pragma unroll
    for (int q = 0; q < 9; q++) {
        wh0 = fmaxf(wh0, fabsf(refine[2*q]     + m0));
        wh1 = fmaxf(wh1, fabsf(refine[2*q + 1] + m1));
    }
    const size_t OUT_WH  = (size_t)Bn*NCn*HWn;
    const size_t OUT_REG = OUT_WH + (size_t)Bn*2*HWn;
    dout[OUT_WH  + ((size_t)(b*2) + 0)*HWn + hw] = wh0;
    dout[OUT_WH  + ((size_t)(b*2) + 1)*HWn + hw] = wh1;
    dout[OUT_REG + ((size_t)(b*2) + 0)*HWn + hw] = m0;
    dout[OUT_REG + ((size_t)(b*2) + 1)*HWn + hw] = m1;
}

// =====================================================================
extern "C" void kernel_launch(void* const* d_in, const int* in_sizes, int n_in,
                              void* d_out, int out_size)
{
    const float* x = (const float*)d_in[0];
    WPtrs wp;
    wp.w[0] = (const float*)d_in[1];   // cls_w0
    wp.w[1] = (const float*)d_in[5];   // cls_w1
    wp.w[2] = (const float*)d_in[9];   // cls_w2
    wp.w[3] = (const float*)d_in[3];   // reg_w0
    wp.w[4] = (const float*)d_in[7];   // reg_w1
    wp.w[5] = (const float*)d_in[11];  // reg_w2
    wp.w[6] = (const float*)d_in[13];  // init_conv_w
    wp.w[7] = (const float*)d_in[17];  // dcn_cls_w
    wp.w[8] = (const float*)d_in[20];  // dcn_ref_w
    const float* cls_b0      = (const float*)d_in[2];
    const float* cls_b1      = (const float*)d_in[6];
    const float* cls_b2      = (const float*)d_in[10];
    const float* reg_b0      = (const float*)d_in[4];
    const float* reg_b1      = (const float*)d_in[8];
    const float* reg_b2      = (const float*)d_in[12];
    const float* init_conv_b = (const float*)d_in[14];
    const float* init_out_w  = (const float*)d_in[15];
    const float* init_out_b  = (const float*)d_in[16];
    const float* cls_out_w   = (const float*)d_in[18];
    const float* cls_out_b   = (const float*)d_in[19];
    const float* ref_out_w   = (const float*)d_in[21];
    const float* ref_out_b   = (const float*)d_in[22];
    float* out = (float*)d_out;

    bf16 *xH,*xL,*aH,*aL,*bH,*bL,*cH,*cL,*dH,*dL,*clsH,*clsL,*ptsH,*ptsL,*wH,*wL;
    bf16 *s0H,*s0L,*s1H,*s1L;
    float *off, *dcn0, *dcn1;
    cudaGetSymbolAddress((void**)&xH,  g_xH);   cudaGetSymbolAddress((void**)&xL,  g_xL);
    cudaGetSymbolAddress((void**)&aH,  g_aH);   cudaGetSymbolAddress((void**)&aL,  g_aL);
    cudaGetSymbolAddress((void**)&bH,  g_bH);   cudaGetSymbolAddress((void**)&bL,  g_bL);
    cudaGetSymbolAddress((void**)&cH,  g_cH);   cudaGetSymbolAddress((void**)&cL,  g_cL);
    cudaGetSymbolAddress((void**)&dH,  g_dH);   cudaGetSymbolAddress((void**)&dL,  g_dL);
    cudaGetSymbolAddress((void**)&clsH, g_clsH); cudaGetSymbolAddress((void**)&clsL, g_clsL);
    cudaGetSymbolAddress((void**)&ptsH, g_ptsH); cudaGetSymbolAddress((void**)&ptsL, g_ptsL);
    cudaGetSymbolAddress((void**)&wH,  g_wH);   cudaGetSymbolAddress((void**)&wL,  g_wL);
    cudaGetSymbolAddress((void**)&s0H, g_s0H);  cudaGetSymbolAddress((void**)&s0L, g_s0L);
    cudaGetSymbolAddress((void**)&s1H, g_s1H);  cudaGetSymbolAddress((void**)&s1L, g_s1L);
    cudaGetSymbolAddress((void**)&off, g_off);
    cudaGetSymbolAddress((void**)&dcn0, g_dcn0);
    cudaGetSymbolAddress((void**)&dcn1, g_dcn1);

    cudaFuncSetAttribute(conv_kernel,  cudaFuncAttributeMaxDynamicSharedMemorySize, CONV_SMEM);
    cudaFuncSetAttribute(dgemm_kernel, cudaFuncAttributeMaxDynamicSharedMemorySize, CONV_SMEM);

    prep_kernel<<<(PKQ + 9*WSZ)/256, 256>>>(x, wp, xH, xL, wH, wL);

    auto WH = [&](int l) { return (const bf16*)(wH + (size_t)l*WSZ); };
    auto WL = [&](int l) { return (const bf16*)(wL + (size_t)l*WSZ); };

    // dual-conv towers
    {
        ConvJob a{xH, xL, WH(0), WL(0), cls_b0, aH, aL};
        ConvJob b{xH, xL, WH(3), WL(3), reg_b0, cH, cL};
        conv_kernel<<<dim3(256,2,2), 256, CONV_SMEM>>>(a, b);
    }
    {
        ConvJob a{aH, aL, WH(1), WL(1), cls_b1, bH, bL};
        ConvJob b{cH, cL, WH(4), WL(4), reg_b1, dH, dL};
        conv_kernel<<<dim3(256,2,2), 256, CONV_SMEM>>>(a, b);
    }
    {
        ConvJob a{bH, bL, WH(2), WL(2), cls_b2, clsH, clsL};
        ConvJob b{dH, dL, WH(5), WL(5), reg_b2, ptsH, ptsL};
        conv_kernel<<<dim3(256,2,2), 256, CONV_SMEM>>>(a, b);
    }
    // init conv (single job)
    {
        ConvJob a{ptsH, ptsL, WH(6), WL(6), init_conv_b, aH, aL};
        conv_kernel<<<dim3(256,2,1), 256, CONV_SMEM>>>(a, a);
    }
    conv1x1_27_kernel<<<128, 256>>>(aH, aL, init_out_w, init_out_b, off);

    // dcn: standalone dual gather -> dual conv-clone GEMM
    gather_kernel<<<dim3(9*NPIX/8, 1, 2), 256>>>(clsH, clsL, ptsH, ptsL, off,
                                                 s0H, s0L, s1H, s1L);
    dgemm_kernel<<<dim3(256, 2, 2), 256, CONV_SMEM>>>(s0H, s0L, s1H, s1L,
                                                      WH(7), WL(7), WH(8), WL(8),
                                                      dcn0, dcn1);

    conv1x1_cls_kernel<<<dim3(128, 5), 256>>>(dcn0, cls_out_w, cls_out_b, out);
    ref_fused_kernel<<<128, 256>>>(dcn1, ref_out_w, ref_out_b, off, out);
}